// round 2
// baseline (speedup 1.0000x reference)
#include <cuda_runtime.h>
#include <cstdint>
#include <math.h>

#define BB 64
#define TT 4096
#define NTOT (BB*TT*64)

// ------------ device scratch (no allocations allowed) ------------
__device__ double g_red[2];               // sum, sumsq of x
__device__ float  g_scal[2];              // 0.8/mean, 0.8/std
__device__ float2 g_w[96*64];             // [(k*32+i2)*64+oc] = {w[oc][2i2][k], w[oc][2i2+1][k]}
__device__ float  g_c0[64*64*3072];       // conv0 out (B*OC rows, 3069 valid, stride 3072)
__device__ float  g_c1[64*64*1536];       // conv1 out (1533 valid, stride 1536)
__device__ float  g_z0[64*64*1536];       // gauss lvl0 (1535 valid, stride 1536)
__device__ float  g_z1[64*64*768];        // gauss lvl1 (767 valid, stride 768)
__device__ double g_bns[256];             // [lvl*128 + {0:sum,64:sumsq} + oc]
__device__ float  g_bnp[256];             // [lvl*128 + {0:scale,64:shift} + oc]

#define FMA2(a,b,c) asm("fma.rn.f32x2 %0, %1, %2, %0;" : "+l"(a) : "l"(b), "l"(c))

__global__ void k_init() {
    int t = threadIdx.x;
    if (t < 2) g_red[t] = 0.0;
    g_bns[t] = 0.0;
}

__global__ void __launch_bounds__(256) k_reduce(const float* __restrict__ x) {
    float s = 0.f, ss = 0.f;
    const float4* x4 = (const float4*)x;
    const int n4 = NTOT / 4;
    for (int i = blockIdx.x * 256 + threadIdx.x; i < n4; i += gridDim.x * 256) {
        float4 v = x4[i];
        s  += (v.x + v.y) + (v.z + v.w);
        ss += (v.x*v.x + v.y*v.y) + (v.z*v.z + v.w*v.w);
    }
    __shared__ float r1[256], r2[256];
    int tid = threadIdx.x;
    r1[tid] = s; r2[tid] = ss; __syncthreads();
    for (int o = 128; o > 0; o >>= 1) {
        if (tid < o) { r1[tid] += r1[tid+o]; r2[tid] += r2[tid+o]; }
        __syncthreads();
    }
    if (tid == 0) {
        atomicAdd(&g_red[0], (double)r1[0]);
        atomicAdd(&g_red[1], (double)r2[0]);
    }
}

__global__ void k_wnorm(const float* __restrict__ v, const float* __restrict__ g) {
    int oc = threadIdx.x;   // 64 threads
    float s = 0.f;
    for (int kk = 0; kk < 192; kk++) { float vv = v[oc*192+kk]; s += vv*vv; }
    float sc = g[oc] / sqrtf(s);
    for (int k = 0; k < 3; k++)
        for (int i2 = 0; i2 < 32; i2++)
            g_w[(k*32+i2)*64 + oc] = make_float2(sc * v[oc*192 + (2*i2)*3 + k],
                                                 sc * v[oc*192 + (2*i2+1)*3 + k]);
    if (oc == 0) {
        double su = g_red[0], ssq = g_red[1];
        double N = (double)NTOT;
        double m = su / N;
        double var = (ssq - su*su/N) / (N - 1.0);
        g_scal[0] = (float)(0.8 / m);
        g_scal[1] = (float)(0.8 / sqrt(var));
    }
}

// conv: joined[u][i]; s=u/3, r=u%3. r0: cm*xn+0.2*prev, r1: prev, r2: cs*xn+0.2*prev
// lvl0: prev t=2s, xn t=2s+1 (L=2048). lvl1: prev t=4s, xn t=4s+3 (L=1024).
// out[o][oc] = sum_{i,k} w[oc][i][k] * joined[2o+3k][i]
template<int LEVEL>
__global__ void __launch_bounds__(256, 1) k_conv(const float* __restrict__ x) {
    constexpr int L    = LEVEL ? 1024 : 2048;
    constexpr int OCL  = LEVEL ? 1533 : 3069;
    constexpr int OSTR = LEVEL ? 1536 : 3072;
    float* cout = LEVEL ? g_c1 : g_c0;

    extern __shared__ float smn[];
    float*  sj = smn;                          // [261][64]
    float2* ws = (float2*)(smn + 261*64);      // [96][64]

    const int tid = threadIdx.x;
    const int b   = blockIdx.y;
    const int o0  = blockIdx.x * 128;
    const float cm = g_scal[0], cs = g_scal[1];

    for (int e = tid; e < 96*64; e += 256) ws[e] = g_w[e];

    const float* xb = x + (size_t)b * (TT*64);
    for (int e = tid; e < 261*64; e += 256) {
        int ul = e >> 6, c = e & 63;
        int u = 2*o0 + ul;
        int s = u / 3;
        int r = u - 3*s;
        float val = 0.f;
        if (s < L) {
            int tp = LEVEL ? (s << 2) : (s << 1);
            float p = xb[tp*64 + c];
            if (r == 1) val = p;
            else {
                int ta = LEVEL ? (4*s + 3) : (2*s + 1);
                float a = xb[ta*64 + c];
                val = fmaf(r == 0 ? cm : cs, a, 0.2f * p);
            }
        }
        sj[ul*64 + c] = val;
    }
    __syncthreads();

    const int g  = tid & 31;      // oc pair {2g, 2g+1}
    const int og = tid >> 5;      // 0..7 -> 16 positions each
    const int ob = og * 16;
    unsigned long long acc[16][2];
    #pragma unroll
    for (int ol = 0; ol < 16; ol++) { acc[ol][0] = 0ULL; acc[ol][1] = 0ULL; }

    const float* sp = sj + ob * 128;   // row 2*ob

    #pragma unroll 1
    for (int i4 = 0; i4 < 16; i4++) {
        #pragma unroll
        for (int k = 0; k < 3; k++) {
            const float2* wp = ws + (k*32 + 2*i4)*64 + 2*g;
            ulonglong2 wa = *(const ulonglong2*)(wp);        // i2=2i4: {oc0, oc1}
            ulonglong2 wb = *(const ulonglong2*)(wp + 64);   // i2=2i4+1
            #pragma unroll
            for (int ol = 0; ol < 16; ol++) {
                ulonglong2 sv = *(const ulonglong2*)(sp + (2*ol + 3*k)*64 + 4*i4);
                FMA2(acc[ol][0], wa.x, sv.x);
                FMA2(acc[ol][1], wa.y, sv.x);
                FMA2(acc[ol][0], wb.x, sv.y);
                FMA2(acc[ol][1], wb.y, sv.y);
            }
        }
    }
    __syncthreads();
    float* ot = sj;   // [64][129] staging
    #pragma unroll
    for (int ol = 0; ol < 16; ol++) {
        float l0, h0, l1, h1;
        asm("mov.b64 {%0, %1}, %2;" : "=f"(l0), "=f"(h0) : "l"(acc[ol][0]));
        asm("mov.b64 {%0, %1}, %2;" : "=f"(l1), "=f"(h1) : "l"(acc[ol][1]));
        int o = ob + ol;
        ot[(2*g)*129 + o]   = l0 + h0;
        ot[(2*g+1)*129 + o] = l1 + h1;
    }
    __syncthreads();
    for (int e = tid; e < 64*128; e += 256) {
        int oc = e >> 7, ol = e & 127;
        int o = o0 + ol;
        if (o < OCL) cout[((size_t)(b*64 + oc))*OSTR + o] = ot[oc*129 + ol];
    }
}

template<int LEVEL>
__global__ void __launch_bounds__(256) k_pool(const float* __restrict__ bias) {
    constexpr int P    = LEVEL ? 767  : 1535;
    constexpr int PSTR = LEVEL ? 768  : 1536;
    constexpr int OCL  = LEVEL ? 1533 : 3069;
    constexpr int OSTR = LEVEL ? 1536 : 3072;
    constexpr int DUP  = LEVEL ? 512  : 1024;
    const float* cin = LEVEL ? g_c1 : g_c0;
    float* z = LEVEL ? g_z1 : g_z0;

    int row = blockIdx.y;            // b*64 + oc
    int oc  = row & 63;
    int tid = threadIdx.x;
    int p   = blockIdx.x * 256 + tid;
    float sv = 0.f, ssv = 0.f;
    if (p < P) {
        const float* cr = cin + (size_t)row * OSTR;
        float m = cr[2*p];
        if (p > 0)         m = fmaxf(m, cr[2*p - 1]);
        if (2*p + 1 < OCL) m = fmaxf(m, cr[2*p + 1]);
        m += bias[oc];
        float e  = m > 0.f ? m : expm1f(m);
        float zz = expf(-0.5f * e * e);
        z[(size_t)row * PSTR + p] = zz;
        float w = (p <= DUP && !(p & 1)) ? 2.f : 1.f;
        sv = w * zz; ssv = w * zz * zz;
    }
    __shared__ float r1[256], r2[256];
    r1[tid] = sv; r2[tid] = ssv; __syncthreads();
    for (int o = 128; o > 0; o >>= 1) {
        if (tid < o) { r1[tid] += r1[tid+o]; r2[tid] += r2[tid+o]; }
        __syncthreads();
    }
    if (tid == 0) {
        atomicAdd(&g_bns[LEVEL*128 + oc],      (double)r1[0]);
        atomicAdd(&g_bns[LEVEL*128 + 64 + oc], (double)r2[0]);
    }
}

__global__ void k_bnfin(const float* __restrict__ gamma, const float* __restrict__ beta) {
    int oc = threadIdx.x;    // 64 threads
    #pragma unroll
    for (int l = 0; l < 2; l++) {
        double cnt = l ? 65536.0 : 131072.0;
        double su = g_bns[l*128 + oc], ssq = g_bns[l*128 + 64 + oc];
        double mu = su / cnt;
        double var = ssq / cnt - mu*mu;
        double inv = 1.0 / sqrt(var + 1e-5);
        g_bnp[l*128 + oc]      = (float)((double)gamma[oc] * inv);
        g_bnp[l*128 + 64 + oc] = (float)((double)beta[oc] - mu * (double)gamma[oc] * inv);
    }
}

// final assembly: sew-up of L1 (a, len 2048) and L0 (b, len 4096) into 6144.
__global__ void __launch_bounds__(256) k_asm(const float* __restrict__ x,
                                             float* __restrict__ out) {
    __shared__ float tile[64][65];
    __shared__ int sT[64];
    __shared__ int sPL[64];   // p*2 + lvl, or -1
    int b  = blockIdx.y;
    int f0 = blockIdx.x * 64;
    int tid = threadIdx.x;

    if (tid < 64) {
        int f = f0 + tid;
        int part, j;
        if (f == 0)      { part = 0; j = 0; }
        else if (f == 1) { part = 1; j = 0; }
        else if (f < 5462) {
            int k = (f - 2) / 12;
            int r = (f - 2) - 12*k;
            if      (r < 4)   { part = 0; j = 9*k + 1 + r; }
            else if (r == 4)  { part = 1; j = 3*k + 1; }
            else if (r < 9)   { part = 0; j = 9*k + r; }
            else if (r == 9)  { part = 1; j = 3*k + 2; }
            else if (r == 10) { part = 0; j = 9*k + 9; }
            else              { part = 1; j = 3*k + 3; }
        } else { part = 1; j = 1366 + (f - 5462); }
        int t, pl = -1;
        if (part == 0) {            // L0: t=j, odd j adds y (level 0)
            t = j;
            if (j & 1) {
                int q = j >> 1;
                int p = (q < 1539) ? 2*(q/3) + ((q % 3) == 2) : q - 513;
                pl = p*2;
            }
        } else {                    // L1: t=2j+(j&1), odd j adds y (level 1)
            t = 2*j + (j & 1);
            if (j & 1) {
                int q = j >> 1;
                int p = (q < 771) ? 2*(q/3) + ((q % 3) == 2) : q - 257;
                pl = p*2 + 1;
            }
        }
        sT[tid] = t; sPL[tid] = pl;
    }
    __syncthreads();

    const float* xb = x + (size_t)b * (TT*64);
    int c = tid & 63, fg = tid >> 6;
    #pragma unroll
    for (int it = 0; it < 16; it++) {
        int fl = fg * 16 + it;
        tile[fl][c] = xb[sT[fl]*64 + c];
    }
    __syncthreads();

    for (int it = 0; it < 16; it++) {
        int e  = it * 256 + tid;
        int cc = e >> 6, fl = e & 63;
        float v = tile[fl][cc];
        int pl = sPL[fl];
        if (pl >= 0) {
            int lvl = pl & 1, p = pl >> 1;
            const float* z = lvl ? g_z1 : g_z0;
            int stride = lvl ? 768 : 1536;
            float zz = z[(size_t)(b*64 + cc)*stride + p];
            float sc = g_bnp[lvl*128 + cc], sh = g_bnp[lvl*128 + 64 + cc];
            float bn = fmaf(sc, zz, sh);
            v += bn > 0.f ? bn : expm1f(bn);
        }
        out[((size_t)(b*64 + cc))*6144 + f0 + fl] = v;
    }
}

extern "C" void kernel_launch(void* const* d_in, const int* in_sizes, int n_in,
                              void* d_out, int out_size) {
    const float* x        = (const float*)d_in[0];
    const float* conv_v   = (const float*)d_in[1];
    const float* conv_g   = (const float*)d_in[2];
    const float* conv_b   = (const float*)d_in[3];
    const float* bn_gamma = (const float*)d_in[4];
    const float* bn_beta  = (const float*)d_in[5];
    float* out = (float*)d_out;

    const int SMEM = 261*64*4 + 96*64*8;   // 115968 B
    cudaFuncSetAttribute(k_conv<0>, cudaFuncAttributeMaxDynamicSharedMemorySize, SMEM);
    cudaFuncSetAttribute(k_conv<1>, cudaFuncAttributeMaxDynamicSharedMemorySize, SMEM);

    k_init<<<1, 256>>>();
    k_reduce<<<1024, 256>>>(x);
    k_wnorm<<<1, 64>>>(conv_v, conv_g);
    k_conv<0><<<dim3(24, 64), 256, SMEM>>>(x);
    k_conv<1><<<dim3(12, 64), 256, SMEM>>>(x);
    k_pool<0><<<dim3(6, 4096), 256>>>(conv_b);
    k_pool<1><<<dim3(3, 4096), 256>>>(conv_b);
    k_bnfin<<<1, 64>>>(bn_gamma, bn_beta);
    k_asm<<<dim3(96, 64), 256>>>(x, out);
}

// round 3
// speedup vs baseline: 1.1003x; 1.1003x over previous
#include <cuda_runtime.h>
#include <cstdint>
#include <math.h>

#define BB 64
#define TT 4096
#define NTOT (BB*TT*64)

// ------------ device scratch (no allocations allowed) ------------
__device__ double g_red[2];               // sum, sumsq of x
__device__ float  g_scal[2];              // 0.8/mean, 0.8/std
__device__ float2 g_w[96*64];             // [(k*32+i2)*64+oc] = {w[oc][2i2][k], w[oc][2i2+1][k]}
__device__ float  g_c0[64*64*3072];       // conv0 out (B*OC rows, 3069 valid, stride 3072)
__device__ float  g_c1[64*64*1536];       // conv1 out (1533 valid, stride 1536)
__device__ float  g_z0[64*64*1536];       // gauss lvl0 (1535 valid, stride 1536)
__device__ float  g_z1[64*64*768];        // gauss lvl1 (767 valid, stride 768)
__device__ double g_bns[256];             // [lvl*128 + {0:sum,64:sumsq} + oc]
__device__ float  g_bnp[256];             // [lvl*128 + {0:scale,64:shift} + oc]

#define FMA2(a,b,c) asm("fma.rn.f32x2 %0, %1, %2, %0;" : "+l"(a) : "l"(b), "l"(c))

__global__ void k_init() {
    int t = threadIdx.x;
    if (t < 2) g_red[t] = 0.0;
    g_bns[t] = 0.0;
}

__global__ void __launch_bounds__(256) k_reduce(const float* __restrict__ x) {
    float s = 0.f, ss = 0.f;
    const float4* x4 = (const float4*)x;
    const int n4 = NTOT / 4;
    for (int i = blockIdx.x * 256 + threadIdx.x; i < n4; i += gridDim.x * 256) {
        float4 v = x4[i];
        s  += (v.x + v.y) + (v.z + v.w);
        ss += (v.x*v.x + v.y*v.y) + (v.z*v.z + v.w*v.w);
    }
    __shared__ float r1[256], r2[256];
    int tid = threadIdx.x;
    r1[tid] = s; r2[tid] = ss; __syncthreads();
    for (int o = 128; o > 0; o >>= 1) {
        if (tid < o) { r1[tid] += r1[tid+o]; r2[tid] += r2[tid+o]; }
        __syncthreads();
    }
    if (tid == 0) {
        atomicAdd(&g_red[0], (double)r1[0]);
        atomicAdd(&g_red[1], (double)r2[0]);
    }
}

__global__ void k_wnorm(const float* __restrict__ v, const float* __restrict__ g) {
    int oc = threadIdx.x;   // 64 threads
    float s = 0.f;
    for (int kk = 0; kk < 192; kk++) { float vv = v[oc*192+kk]; s += vv*vv; }
    float sc = g[oc] / sqrtf(s);
    for (int k = 0; k < 3; k++)
        for (int i2 = 0; i2 < 32; i2++)
            g_w[(k*32+i2)*64 + oc] = make_float2(sc * v[oc*192 + (2*i2)*3 + k],
                                                 sc * v[oc*192 + (2*i2+1)*3 + k]);
    if (oc == 0) {
        double su = g_red[0], ssq = g_red[1];
        double N = (double)NTOT;
        double m = su / N;
        double var = (ssq - su*su/N) / (N - 1.0);
        g_scal[0] = (float)(0.8 / m);
        g_scal[1] = (float)(0.8 / sqrt(var));
    }
}

// conv: joined[u][i]; s=u/3, r=u%3. r0: cm*xn+0.2*prev, r1: prev, r2: cs*xn+0.2*prev
// lvl0: prev t=2s, xn t=2s+1 (L=2048). lvl1: prev t=4s, xn t=4s+3 (L=1024).
// out[o][oc] = sum_{i,k} w[oc][i][k] * joined[2o+3k][i]
template<int LEVEL>
__global__ void __launch_bounds__(512, 1) k_conv(const float* __restrict__ x) {
    constexpr int L    = LEVEL ? 1024 : 2048;
    constexpr int OCL  = LEVEL ? 1533 : 3069;
    constexpr int OSTR = LEVEL ? 1536 : 3072;
    float* cout = LEVEL ? g_c1 : g_c0;

    extern __shared__ float smn[];
    float*  sj = smn;                          // [261][64]
    float2* ws = (float2*)(smn + 261*64);      // [96][64]

    const int tid = threadIdx.x;
    const int b   = blockIdx.y;
    const int o0  = blockIdx.x * 128;
    const float cm = g_scal[0], cs = g_scal[1];

    for (int e = tid; e < 96*64; e += 512) ws[e] = g_w[e];

    const float* xb = x + (size_t)b * (TT*64);
    for (int e = tid; e < 261*64; e += 512) {
        int ul = e >> 6, c = e & 63;
        int u = 2*o0 + ul;
        int s = u / 3;
        int r = u - 3*s;
        float val = 0.f;
        if (s < L) {
            int tp = LEVEL ? (s << 2) : (s << 1);
            float p = xb[tp*64 + c];
            if (r == 1) val = p;
            else {
                int ta = LEVEL ? (4*s + 3) : (2*s + 1);
                float a = xb[ta*64 + c];
                val = fmaf(r == 0 ? cm : cs, a, 0.2f * p);
            }
        }
        sj[ul*64 + c] = val;
    }
    __syncthreads();

    const int g  = tid & 31;      // oc pair {2g, 2g+1}
    const int og = tid >> 5;      // 0..15 -> 8 positions each
    const int ob = og * 8;
    unsigned long long acc[8][2];
    #pragma unroll
    for (int ol = 0; ol < 8; ol++) { acc[ol][0] = 0ULL; acc[ol][1] = 0ULL; }

    const float* sp = sj + ob * 128;   // row 2*ob

    #pragma unroll 1
    for (int i4 = 0; i4 < 16; i4++) {
        #pragma unroll
        for (int k = 0; k < 3; k++) {
            const float2* wp = ws + (k*32 + 2*i4)*64 + 2*g;
            ulonglong2 wa = *(const ulonglong2*)(wp);        // i2=2i4: {oc0, oc1}
            ulonglong2 wb = *(const ulonglong2*)(wp + 64);   // i2=2i4+1
            #pragma unroll
            for (int ol = 0; ol < 8; ol++) {
                ulonglong2 sv = *(const ulonglong2*)(sp + (2*ol + 3*k)*64 + 4*i4);
                FMA2(acc[ol][0], wa.x, sv.x);
                FMA2(acc[ol][1], wa.y, sv.x);
                FMA2(acc[ol][0], wb.x, sv.y);
                FMA2(acc[ol][1], wb.y, sv.y);
            }
        }
    }
    __syncthreads();
    float* ot = sj;   // [64][129] staging
    #pragma unroll
    for (int ol = 0; ol < 8; ol++) {
        float l0, h0, l1, h1;
        asm("mov.b64 {%0, %1}, %2;" : "=f"(l0), "=f"(h0) : "l"(acc[ol][0]));
        asm("mov.b64 {%0, %1}, %2;" : "=f"(l1), "=f"(h1) : "l"(acc[ol][1]));
        int o = ob + ol;
        ot[(2*g)*129 + o]   = l0 + h0;
        ot[(2*g+1)*129 + o] = l1 + h1;
    }
    __syncthreads();
    for (int e = tid; e < 64*128; e += 512) {
        int oc = e >> 7, ol = e & 127;
        int o = o0 + ol;
        if (o < OCL) cout[((size_t)(b*64 + oc))*OSTR + o] = ot[oc*129 + ol];
    }
}

template<int LEVEL>
__global__ void __launch_bounds__(256) k_pool(const float* __restrict__ bias) {
    constexpr int P    = LEVEL ? 767  : 1535;
    constexpr int PSTR = LEVEL ? 768  : 1536;
    constexpr int OCL  = LEVEL ? 1533 : 3069;
    constexpr int OSTR = LEVEL ? 1536 : 3072;
    constexpr int DUP  = LEVEL ? 512  : 1024;
    const float* cin = LEVEL ? g_c1 : g_c0;
    float* z = LEVEL ? g_z1 : g_z0;

    int row = blockIdx.y;            // b*64 + oc
    int oc  = row & 63;
    int tid = threadIdx.x;
    int p   = blockIdx.x * 256 + tid;
    float sv = 0.f, ssv = 0.f;
    if (p < P) {
        const float* cr = cin + (size_t)row * OSTR;
        float m = cr[2*p];
        if (p > 0)         m = fmaxf(m, cr[2*p - 1]);
        if (2*p + 1 < OCL) m = fmaxf(m, cr[2*p + 1]);
        m += bias[oc];
        float e  = m > 0.f ? m : expm1f(m);
        float zz = expf(-0.5f * e * e);
        z[(size_t)row * PSTR + p] = zz;
        float w = (p <= DUP && !(p & 1)) ? 2.f : 1.f;
        sv = w * zz; ssv = w * zz * zz;
    }
    __shared__ float r1[256], r2[256];
    r1[tid] = sv; r2[tid] = ssv; __syncthreads();
    for (int o = 128; o > 0; o >>= 1) {
        if (tid < o) { r1[tid] += r1[tid+o]; r2[tid] += r2[tid+o]; }
        __syncthreads();
    }
    if (tid == 0) {
        atomicAdd(&g_bns[LEVEL*128 + oc],      (double)r1[0]);
        atomicAdd(&g_bns[LEVEL*128 + 64 + oc], (double)r2[0]);
    }
}

__global__ void k_bnfin(const float* __restrict__ gamma, const float* __restrict__ beta) {
    int oc = threadIdx.x;    // 64 threads
    #pragma unroll
    for (int l = 0; l < 2; l++) {
        double cnt = l ? 65536.0 : 131072.0;
        double su = g_bns[l*128 + oc], ssq = g_bns[l*128 + 64 + oc];
        double mu = su / cnt;
        double var = ssq / cnt - mu*mu;
        double inv = 1.0 / sqrt(var + 1e-5);
        g_bnp[l*128 + oc]      = (float)((double)gamma[oc] * inv);
        g_bnp[l*128 + 64 + oc] = (float)((double)beta[oc] - mu * (double)gamma[oc] * inv);
    }
}

// final assembly: sew-up of L1 (a, len 2048) and L0 (b, len 4096) into 6144.
__global__ void __launch_bounds__(256) k_asm(const float* __restrict__ x,
                                             float* __restrict__ out) {
    __shared__ float tile[64][65];
    __shared__ int sT[64];
    __shared__ int sPL[64];   // p*2 + lvl, or -1
    int b  = blockIdx.y;
    int f0 = blockIdx.x * 64;
    int tid = threadIdx.x;

    if (tid < 64) {
        int f = f0 + tid;
        int part, j;
        if (f == 0)      { part = 0; j = 0; }
        else if (f == 1) { part = 1; j = 0; }
        else if (f < 5462) {
            int k = (f - 2) / 12;
            int r = (f - 2) - 12*k;
            if      (r < 4)   { part = 0; j = 9*k + 1 + r; }
            else if (r == 4)  { part = 1; j = 3*k + 1; }
            else if (r < 9)   { part = 0; j = 9*k + r; }
            else if (r == 9)  { part = 1; j = 3*k + 2; }
            else if (r == 10) { part = 0; j = 9*k + 9; }
            else              { part = 1; j = 3*k + 3; }
        } else { part = 1; j = 1366 + (f - 5462); }
        int t, pl = -1;
        if (part == 0) {            // L0: t=j, odd j adds y (level 0)
            t = j;
            if (j & 1) {
                int q = j >> 1;
                int p = (q < 1539) ? 2*(q/3) + ((q % 3) == 2) : q - 513;
                pl = p*2;
            }
        } else {                    // L1: t=2j+(j&1), odd j adds y (level 1)
            t = 2*j + (j & 1);
            if (j & 1) {
                int q = j >> 1;
                int p = (q < 771) ? 2*(q/3) + ((q % 3) == 2) : q - 257;
                pl = p*2 + 1;
            }
        }
        sT[tid] = t; sPL[tid] = pl;
    }
    __syncthreads();

    const float* xb = x + (size_t)b * (TT*64);
    int c = tid & 63, fg = tid >> 6;
    #pragma unroll
    for (int it = 0; it < 16; it++) {
        int fl = fg * 16 + it;
        tile[fl][c] = xb[sT[fl]*64 + c];
    }
    __syncthreads();

    for (int it = 0; it < 16; it++) {
        int e  = it * 256 + tid;
        int cc = e >> 6, fl = e & 63;
        float v = tile[fl][cc];
        int pl = sPL[fl];
        if (pl >= 0) {
            int lvl = pl & 1, p = pl >> 1;
            const float* z = lvl ? g_z1 : g_z0;
            int stride = lvl ? 768 : 1536;
            float zz = z[(size_t)(b*64 + cc)*stride + p];
            float sc = g_bnp[lvl*128 + cc], sh = g_bnp[lvl*128 + 64 + cc];
            float bn = fmaf(sc, zz, sh);
            v += bn > 0.f ? bn : expm1f(bn);
        }
        out[((size_t)(b*64 + cc))*6144 + f0 + fl] = v;
    }
}

extern "C" void kernel_launch(void* const* d_in, const int* in_sizes, int n_in,
                              void* d_out, int out_size) {
    const float* x        = (const float*)d_in[0];
    const float* conv_v   = (const float*)d_in[1];
    const float* conv_g   = (const float*)d_in[2];
    const float* conv_b   = (const float*)d_in[3];
    const float* bn_gamma = (const float*)d_in[4];
    const float* bn_beta  = (const float*)d_in[5];
    float* out = (float*)d_out;

    const int SMEM = 261*64*4 + 96*64*8;   // 115968 B
    cudaFuncSetAttribute(k_conv<0>, cudaFuncAttributeMaxDynamicSharedMemorySize, SMEM);
    cudaFuncSetAttribute(k_conv<1>, cudaFuncAttributeMaxDynamicSharedMemorySize, SMEM);

    k_init<<<1, 256>>>();
    k_reduce<<<1024, 256>>>(x);
    k_wnorm<<<1, 64>>>(conv_v, conv_g);
    k_conv<0><<<dim3(24, 64), 512, SMEM>>>(x);
    k_conv<1><<<dim3(12, 64), 512, SMEM>>>(x);
    k_pool<0><<<dim3(6, 4096), 256>>>(conv_b);
    k_pool<1><<<dim3(3, 4096), 256>>>(conv_b);
    k_bnfin<<<1, 64>>>(bn_gamma, bn_beta);
    k_asm<<<dim3(96, 64), 256>>>(x, out);
}

// round 5
// speedup vs baseline: 1.2786x; 1.1620x over previous
#include <cuda_runtime.h>
#include <cuda_fp16.h>
#include <cstdint>
#include <math.h>

#define BB 64
#define TT 4096
#define NTOT (BB*TT*64)

// ------------ device scratch ------------
__device__ double   g_red[2];
__device__ float    g_scal[4];            // cm, cs, 0.2/cm, 0.2/cs
__device__ uint32_t g_wimg[2*6144];       // B images (hi, lo), 24KB each, pre-swizzled fp16x2
__device__ float    g_c0[64*64*3072];
__device__ float    g_c1[64*64*1536];
__device__ float    g_z0[64*64*1536];
__device__ float    g_z1[64*64*768];
__device__ double   g_bns[256];
__device__ float    g_bnp[256];

#define SWZ128(o) ((o) ^ (((o) >> 3) & 0x70))

__device__ __forceinline__ uint32_t smem_u32(const void* p) {
    uint32_t a;
    asm("{ .reg .u64 t; cvta.to.shared.u64 t, %1; cvt.u32.u64 %0, t; }" : "=r"(a) : "l"(p));
    return a;
}

#define LDSM4(r, a) asm volatile( \
    "ldmatrix.sync.aligned.m8n8.x4.shared.b16 {%0,%1,%2,%3}, [%4];" \
    : "=r"((r)[0]), "=r"((r)[1]), "=r"((r)[2]), "=r"((r)[3]) : "r"(a))

#define MMA16816(d, a, b0, b1) asm volatile( \
    "mma.sync.aligned.m16n8k16.row.col.f32.f16.f16.f32 " \
    "{%0,%1,%2,%3}, {%4,%5,%6,%7}, {%8,%9}, {%0,%1,%2,%3};" \
    : "+f"((d)[0]), "+f"((d)[1]), "+f"((d)[2]), "+f"((d)[3]) \
    : "r"((a)[0]), "r"((a)[1]), "r"((a)[2]), "r"((a)[3]), "r"(b0), "r"(b1))

__device__ __forceinline__ uint32_t packsplit(float vx, float vy, uint32_t& lo) {
    __half h0 = __float2half_rn(vx); float r0 = vx - __half2float(h0);
    __half h1 = __float2half_rn(vy); float r1 = vy - __half2float(h1);
    __half g0 = __float2half_rn(r0);
    __half g1 = __float2half_rn(r1);
    lo = (uint32_t)__half_as_ushort(g0) | ((uint32_t)__half_as_ushort(g1) << 16);
    return (uint32_t)__half_as_ushort(h0) | ((uint32_t)__half_as_ushort(h1) << 16);
}

// ------------ small kernels ------------
__global__ void k_init() {
    int t = threadIdx.x;
    if (t < 2) g_red[t] = 0.0;
    g_bns[t] = 0.0;
}

__global__ void __launch_bounds__(256) k_reduce(const float* __restrict__ x) {
    float s = 0.f, ss = 0.f;
    const float4* x4 = (const float4*)x;
    const int n4 = NTOT / 4;
    for (int i = blockIdx.x * 256 + threadIdx.x; i < n4; i += gridDim.x * 256) {
        float4 v = x4[i];
        s  += (v.x + v.y) + (v.z + v.w);
        ss += (v.x*v.x + v.y*v.y) + (v.z*v.z + v.w*v.w);
    }
    __shared__ float r1[256], r2[256];
    int tid = threadIdx.x;
    r1[tid] = s; r2[tid] = ss; __syncthreads();
    for (int o = 128; o > 0; o >>= 1) {
        if (tid < o) { r1[tid] += r1[tid+o]; r2[tid] += r2[tid+o]; }
        __syncthreads();
    }
    if (tid == 0) {
        atomicAdd(&g_red[0], (double)r1[0]);
        atomicAdd(&g_red[1], (double)r2[0]);
    }
}

// weight-norm + build swizzled fp16 hi/lo B images: B[oc][kk = k*64 + i]
__global__ void k_wnorm(const float* __restrict__ v, const float* __restrict__ g) {
    int oc = threadIdx.x;   // 64 threads
    float s = 0.f;
    for (int kk = 0; kk < 192; kk++) { float vv = v[oc*192+kk]; s += vv*vv; }
    float sc = g[oc] / sqrtf(s);
    for (int k = 0; k < 3; k++) {
        for (int ii = 0; ii < 32; ii++) {
            float w0 = sc * v[oc*192 + (2*ii)*3 + k];
            float w1 = sc * v[oc*192 + (2*ii+1)*3 + k];
            uint32_t lo, hi = packsplit(w0, w1, lo);
            int byt = (k*8 + (oc >> 3))*1024 + SWZ128((oc & 7)*128 + ii*4);
            g_wimg[byt >> 2]        = hi;
            g_wimg[6144 + (byt >> 2)] = lo;
        }
    }
    if (oc == 0) {
        double su = g_red[0], ssq = g_red[1];
        double N = (double)NTOT;
        double m = su / N;
        double var = (ssq - su*su/N) / (N - 1.0);
        g_scal[0] = (float)(0.8 / m);
        g_scal[1] = (float)(0.8 / sqrt(var));
        g_scal[2] = (float)(0.2 * m / 0.8);
        g_scal[3] = (float)(0.2 * sqrt(var) / 0.8);
    }
}

// ------------ tensor-core conv via mma.sync ------------
// D[m 0..127][oc 0..63] = sum_kk A[m][kk]*B[oc][kk], K = 192 (kk = k*64 + i)
// smem: Ahi@0 (48KB), Alo@49152, Bhi@98304 (24KB), Blo@122880. total 147456.
#define SM_ALO 49152
#define SM_B   98304
#define SMEM_MMA 147456

template<int LEVEL>
__global__ void __launch_bounds__(256, 1) k_convmma(const float* __restrict__ x) {
    constexpr int L    = LEVEL ? 1024 : 2048;
    constexpr int OCL  = LEVEL ? 1533 : 3069;
    constexpr int OSTR = LEVEL ? 1536 : 3072;
    float* cout = LEVEL ? g_c1 : g_c0;

    extern __shared__ char sm[];
    const int tid = threadIdx.x, wid = tid >> 5, lane = tid & 31;
    const int b = blockIdx.y, o0 = blockIdx.x * 128;

    // B images (48KB) from gmem
    {
        const uint4* wi = (const uint4*)g_wimg;
        uint4* bs = (uint4*)(sm + SM_B);
        #pragma unroll
        for (int it = 0; it < 12; it++) bs[tid + it*256] = wi[tid + it*256];
    }

    // build A hi/lo images: 128 rows x 96 channel-pairs
    const float f0c = g_scal[2], f2c = g_scal[3];
    const float2* xb2 = (const float2*)(x + (size_t)b * (TT*64));
    for (int e = tid; e < 12288; e += 256) {
        int m = e / 96, rem = e - m*96;
        int k = rem >> 5, ii = rem & 31;
        int u2 = (o0 + m) * 2;
        int r  = u2 % 3;
        int s  = u2 / 3 + k;
        float2 va = make_float2(0.f, 0.f);
        if (s < L) {
            int tp = LEVEL ? (s << 2) : (s << 1);
            float2 p = xb2[tp*32 + ii];
            if (r == 1) va = p;
            else {
                int ta = LEVEL ? (4*s + 3) : (2*s + 1);
                float2 a = xb2[ta*32 + ii];
                float f = (r == 0) ? f0c : f2c;
                va.x = fmaf(f, p.x, a.x);
                va.y = fmaf(f, p.y, a.y);
            }
        }
        uint32_t lo, hi = packsplit(va.x, va.y, lo);
        int byt = (k*16 + (m >> 3))*1024 + SWZ128((m & 7)*128 + ii*4);
        *(uint32_t*)(sm + byt)          = hi;
        *(uint32_t*)(sm + SM_ALO + byt) = lo;
    }
    __syncthreads();

    // mainloop: warp wid -> mblock = wid&3 (32 rows), nhalf = wid>>2 (32 oc)
    const uint32_t sbase = smem_u32(sm);
    const int mb = wid & 3, nh = wid >> 2;
    const int l16 = lane & 15, lhi = lane >> 4;

    uint32_t pa[2], pb[2];   // base (atom-row) + fixed swizzled offset, colb XORed per step
    #pragma unroll
    for (int t = 0; t < 2; t++) {
        int arow = mb*32 + t*16 + l16;
        pa[t] = sbase + (uint32_t)((arow >> 3)*1024)
              + ((uint32_t)(((arow & 7)*128) | (lhi*16)) ^ (uint32_t)((arow & 7) << 4));
        int brow = nh*32 + t*16 + l16;
        pb[t] = sbase + SM_B + (uint32_t)((brow >> 3)*1024)
              + ((uint32_t)(((brow & 7)*128) | (lhi*16)) ^ (uint32_t)((brow & 7) << 4));
    }

    float d[2][4][4];
    #pragma unroll
    for (int i = 0; i < 2; i++)
        #pragma unroll
        for (int j = 0; j < 4; j++)
            #pragma unroll
            for (int q = 0; q < 4; q++) d[i][j][q] = 0.f;

    #pragma unroll 1
    for (int s = 0; s < 12; s++) {
        uint32_t ao = (uint32_t)(s >> 2) * 16384;
        uint32_t bo = (uint32_t)(s >> 2) * 8192;
        uint32_t cb = (uint32_t)(s & 3) * 32;
        uint32_t AH0[4], AH1[4], AL0[4], AL1[4];
        uint32_t BH0[4], BH1[4], BL0[4], BL1[4];
        uint32_t a0 = (pa[0] ^ cb) + ao, a1 = (pa[1] ^ cb) + ao;
        uint32_t b0 = (pb[0] ^ cb) + bo, b1 = (pb[1] ^ cb) + bo;
        LDSM4(AH0, a0);          LDSM4(AH1, a1);
        LDSM4(AL0, a0 + SM_ALO); LDSM4(AL1, a1 + SM_ALO);
        LDSM4(BH0, b0);          LDSM4(BH1, b1);
        LDSM4(BL0, b0 + 24576);  LDSM4(BL1, b1 + 24576);

        // pass1: Ah*Bh
        MMA16816(d[0][0], AH0, BH0[0], BH0[2]);
        MMA16816(d[0][1], AH0, BH0[1], BH0[3]);
        MMA16816(d[0][2], AH0, BH1[0], BH1[2]);
        MMA16816(d[0][3], AH0, BH1[1], BH1[3]);
        MMA16816(d[1][0], AH1, BH0[0], BH0[2]);
        MMA16816(d[1][1], AH1, BH0[1], BH0[3]);
        MMA16816(d[1][2], AH1, BH1[0], BH1[2]);
        MMA16816(d[1][3], AH1, BH1[1], BH1[3]);
        // pass2: Ah*Bl
        MMA16816(d[0][0], AH0, BL0[0], BL0[2]);
        MMA16816(d[0][1], AH0, BL0[1], BL0[3]);
        MMA16816(d[0][2], AH0, BL1[0], BL1[2]);
        MMA16816(d[0][3], AH0, BL1[1], BL1[3]);
        MMA16816(d[1][0], AH1, BL0[0], BL0[2]);
        MMA16816(d[1][1], AH1, BL0[1], BL0[3]);
        MMA16816(d[1][2], AH1, BL1[0], BL1[2]);
        MMA16816(d[1][3], AH1, BL1[1], BL1[3]);
        // pass3: Al*Bh
        MMA16816(d[0][0], AL0, BH0[0], BH0[2]);
        MMA16816(d[0][1], AL0, BH0[1], BH0[3]);
        MMA16816(d[0][2], AL0, BH1[0], BH1[2]);
        MMA16816(d[0][3], AL0, BH1[1], BH1[3]);
        MMA16816(d[1][0], AL1, BH0[0], BH0[2]);
        MMA16816(d[1][1], AL1, BH0[1], BH0[3]);
        MMA16816(d[1][2], AL1, BH1[0], BH1[2]);
        MMA16816(d[1][3], AL1, BH1[1], BH1[3]);
    }
    __syncthreads();

    // epilogue: scale by row class factor, transpose via smem, store
    const float cm = g_scal[0], cs = g_scal[1];
    float* tp = (float*)sm;                  // [64][132], reuses A region
    #pragma unroll
    for (int mt = 0; mt < 2; mt++) {
        int m0 = mb*32 + mt*16 + (lane >> 2);
        int r0 = (2*(o0 + m0)) % 3;
        int r8 = (2*(o0 + m0 + 8)) % 3;
        float f0 = (r0 == 0) ? cm : ((r0 == 2) ? cs : 1.f);
        float f8 = (r8 == 0) ? cm : ((r8 == 2) ? cs : 1.f);
        #pragma unroll
        for (int nt = 0; nt < 4; nt++) {
            int oc0 = nh*32 + nt*8 + (lane & 3)*2;
            tp[oc0*132 + m0]         = f0 * d[mt][nt][0];
            tp[(oc0+1)*132 + m0]     = f0 * d[mt][nt][1];
            tp[oc0*132 + m0 + 8]     = f8 * d[mt][nt][2];
            tp[(oc0+1)*132 + m0 + 8] = f8 * d[mt][nt][3];
        }
    }
    __syncthreads();
    for (int e = tid; e < 8192; e += 256) {
        int oc = e >> 7, ml = e & 127;
        int o = o0 + ml;
        if (o < OCL) cout[((size_t)(b*64 + oc))*OSTR + o] = tp[oc*132 + ml];
    }
}

// ------------ pool + gauss + BN stats ------------
template<int LEVEL>
__global__ void __launch_bounds__(256) k_pool(const float* __restrict__ bias) {
    constexpr int P    = LEVEL ? 767  : 1535;
    constexpr int PSTR = LEVEL ? 768  : 1536;
    constexpr int OCL  = LEVEL ? 1533 : 3069;
    constexpr int OSTR = LEVEL ? 1536 : 3072;
    constexpr int DUP  = LEVEL ? 512  : 1024;
    const float* cin = LEVEL ? g_c1 : g_c0;
    float* z = LEVEL ? g_z1 : g_z0;

    int row = blockIdx.y;
    int oc  = row & 63;
    int tid = threadIdx.x;
    int p   = blockIdx.x * 256 + tid;
    float sv = 0.f, ssv = 0.f;
    if (p < P) {
        const float* cr = cin + (size_t)row * OSTR;
        float m = cr[2*p];
        if (p > 0)         m = fmaxf(m, cr[2*p - 1]);
        if (2*p + 1 < OCL) m = fmaxf(m, cr[2*p + 1]);
        m += bias[oc];
        float e  = m > 0.f ? m : expm1f(m);
        float zz = expf(-0.5f * e * e);
        z[(size_t)row * PSTR + p] = zz;
        float w = (p <= DUP && !(p & 1)) ? 2.f : 1.f;
        sv = w * zz; ssv = w * zz * zz;
    }
    __shared__ float r1[256], r2[256];
    r1[tid] = sv; r2[tid] = ssv; __syncthreads();
    for (int o = 128; o > 0; o >>= 1) {
        if (tid < o) { r1[tid] += r1[tid+o]; r2[tid] += r2[tid+o]; }
        __syncthreads();
    }
    if (tid == 0) {
        atomicAdd(&g_bns[LEVEL*128 + oc],      (double)r1[0]);
        atomicAdd(&g_bns[LEVEL*128 + 64 + oc], (double)r2[0]);
    }
}

__global__ void k_bnfin(const float* __restrict__ gamma, const float* __restrict__ beta) {
    int oc = threadIdx.x;
    #pragma unroll
    for (int l = 0; l < 2; l++) {
        double cnt = l ? 65536.0 : 131072.0;
        double su = g_bns[l*128 + oc], ssq = g_bns[l*128 + 64 + oc];
        double mu = su / cnt;
        double var = ssq / cnt - mu*mu;
        double inv = 1.0 / sqrt(var + 1e-5);
        g_bnp[l*128 + oc]      = (float)((double)gamma[oc] * inv);
        g_bnp[l*128 + 64 + oc] = (float)((double)beta[oc] - mu * (double)gamma[oc] * inv);
    }
}

// ------------ final assembly ------------
__global__ void __launch_bounds__(256) k_asm(const float* __restrict__ x,
                                             float* __restrict__ out) {
    __shared__ float tile[64][65];
    __shared__ int sT[64];
    __shared__ int sPL[64];
    int b  = blockIdx.y;
    int f0 = blockIdx.x * 64;
    int tid = threadIdx.x;

    if (tid < 64) {
        int f = f0 + tid;
        int part, j;
        if (f == 0)      { part = 0; j = 0; }
        else if (f == 1) { part = 1; j = 0; }
        else if (f < 5462) {
            int k = (f - 2) / 12;
            int r = (f - 2) - 12*k;
            if      (r < 4)   { part = 0; j = 9*k + 1 + r; }
            else if (r == 4)  { part = 1; j = 3*k + 1; }
            else if (r < 9)   { part = 0; j = 9*k + r; }
            else if (r == 9)  { part = 1; j = 3*k + 2; }
            else if (r == 10) { part = 0; j = 9*k + 9; }
            else              { part = 1; j = 3*k + 3; }
        } else { part = 1; j = 1366 + (f - 5462); }
        int t, pl = -1;
        if (part == 0) {
            t = j;
            if (j & 1) {
                int q = j >> 1;
                int p = (q < 1539) ? 2*(q/3) + ((q % 3) == 2) : q - 513;
                pl = p*2;
            }
        } else {
            t = 2*j + (j & 1);
            if (j & 1) {
                int q = j >> 1;
                int p = (q < 771) ? 2*(q/3) + ((q % 3) == 2) : q - 257;
                pl = p*2 + 1;
            }
        }
        sT[tid] = t; sPL[tid] = pl;
    }
    __syncthreads();

    const float* xb = x + (size_t)b * (TT*64);
    int c = tid & 63, fg = tid >> 6;
    #pragma unroll
    for (int it = 0; it < 16; it++) {
        int fl = fg * 16 + it;
        tile[fl][c] = xb[sT[fl]*64 + c];
    }
    __syncthreads();

    for (int it = 0; it < 16; it++) {
        int e  = it * 256 + tid;
        int cc = e >> 6, fl = e & 63;
        float v = tile[fl][cc];
        int pl = sPL[fl];
        if (pl >= 0) {
            int lvl = pl & 1, p = pl >> 1;
            const float* z = lvl ? g_z1 : g_z0;
            int stride = lvl ? 768 : 1536;
            float zz = z[(size_t)(b*64 + cc)*stride + p];
            float sc = g_bnp[lvl*128 + cc], sh = g_bnp[lvl*128 + 64 + cc];
            float bn = fmaf(sc, zz, sh);
            v += bn > 0.f ? bn : expm1f(bn);
        }
        out[((size_t)(b*64 + cc))*6144 + f0 + fl] = v;
    }
}

extern "C" void kernel_launch(void* const* d_in, const int* in_sizes, int n_in,
                              void* d_out, int out_size) {
    const float* x        = (const float*)d_in[0];
    const float* conv_v   = (const float*)d_in[1];
    const float* conv_g   = (const float*)d_in[2];
    const float* conv_b   = (const float*)d_in[3];
    const float* bn_gamma = (const float*)d_in[4];
    const float* bn_beta  = (const float*)d_in[5];
    float* out = (float*)d_out;

    cudaFuncSetAttribute(k_convmma<0>, cudaFuncAttributeMaxDynamicSharedMemorySize, SMEM_MMA);
    cudaFuncSetAttribute(k_convmma<1>, cudaFuncAttributeMaxDynamicSharedMemorySize, SMEM_MMA);

    k_init<<<1, 256>>>();
    k_reduce<<<1024, 256>>>(x);
    k_wnorm<<<1, 64>>>(conv_v, conv_g);
    k_convmma<0><<<dim3(24, 64), 256, SMEM_MMA>>>(x);
    k_convmma<1><<<dim3(12, 64), 256, SMEM_MMA>>>(x);
    k_pool<0><<<dim3(6, 4096), 256>>>(conv_b);
    k_pool<1><<<dim3(3, 4096), 256>>>(conv_b);
    k_bnfin<<<1, 64>>>(bn_gamma, bn_beta);
    k_asm<<<dim3(96, 64), 256>>>(x, out);
}

// round 6
// speedup vs baseline: 1.6078x; 1.2575x over previous
#include <cuda_runtime.h>
#include <cuda_fp16.h>
#include <cstdint>
#include <math.h>

#define BB 64
#define TT 4096
#define NTOT (BB*TT*64)

// ------------ device scratch ------------
__device__ double   g_red[2];
__device__ float    g_scal[4];            // cm, cs, 0.2/cm, 0.2/cs
__device__ uint32_t g_wimg[2*6144];       // B images (hi, lo), 24KB each, pre-swizzled fp16x2
__device__ float    g_c0[64*64*3072];
__device__ float    g_c1[64*64*1536];
__device__ float    g_z0[64*64*1536];
__device__ float    g_z1[64*64*768];
__device__ double   g_bns[256];
__device__ float    g_bnp[256];

#define SWZ128(o) ((o) ^ (((o) >> 3) & 0x70))

__device__ __forceinline__ uint32_t smem_u32(const void* p) {
    uint32_t a;
    asm("{ .reg .u64 t; cvta.to.shared.u64 t, %1; cvt.u32.u64 %0, t; }" : "=r"(a) : "l"(p));
    return a;
}

#define LDSM4(r, a) asm volatile( \
    "ldmatrix.sync.aligned.m8n8.x4.shared.b16 {%0,%1,%2,%3}, [%4];" \
    : "=r"((r)[0]), "=r"((r)[1]), "=r"((r)[2]), "=r"((r)[3]) : "r"(a))

#define MMA16816(d, a, b0, b1) asm volatile( \
    "mma.sync.aligned.m16n8k16.row.col.f32.f16.f16.f32 " \
    "{%0,%1,%2,%3}, {%4,%5,%6,%7}, {%8,%9}, {%0,%1,%2,%3};" \
    : "+f"((d)[0]), "+f"((d)[1]), "+f"((d)[2]), "+f"((d)[3]) \
    : "r"((a)[0]), "r"((a)[1]), "r"((a)[2]), "r"((a)[3]), "r"(b0), "r"(b1))

__device__ __forceinline__ uint32_t packsplit(float vx, float vy, uint32_t& lo) {
    __half h0 = __float2half_rn(vx); float r0 = vx - __half2float(h0);
    __half h1 = __float2half_rn(vy); float r1 = vy - __half2float(h1);
    __half g0 = __float2half_rn(r0);
    __half g1 = __float2half_rn(r1);
    lo = (uint32_t)__half_as_ushort(g0) | ((uint32_t)__half_as_ushort(g1) << 16);
    return (uint32_t)__half_as_ushort(h0) | ((uint32_t)__half_as_ushort(h1) << 16);
}

// ------------ small kernels ------------
__global__ void k_init() {
    int t = threadIdx.x;
    if (t < 2) g_red[t] = 0.0;
    g_bns[t] = 0.0;
}

__global__ void __launch_bounds__(256) k_reduce(const float* __restrict__ x) {
    float s = 0.f, ss = 0.f;
    const float4* x4 = (const float4*)x;
    const int n4 = NTOT / 4;
    for (int i = blockIdx.x * 256 + threadIdx.x; i < n4; i += gridDim.x * 256) {
        float4 v = x4[i];
        s  += (v.x + v.y) + (v.z + v.w);
        ss += (v.x*v.x + v.y*v.y) + (v.z*v.z + v.w*v.w);
    }
    __shared__ float r1[256], r2[256];
    int tid = threadIdx.x;
    r1[tid] = s; r2[tid] = ss; __syncthreads();
    for (int o = 128; o > 0; o >>= 1) {
        if (tid < o) { r1[tid] += r1[tid+o]; r2[tid] += r2[tid+o]; }
        __syncthreads();
    }
    if (tid == 0) {
        atomicAdd(&g_red[0], (double)r1[0]);
        atomicAdd(&g_red[1], (double)r2[0]);
    }
}

// weight-norm + build swizzled fp16 hi/lo B images: B[oc][kk = k*64 + i]
__global__ void k_wnorm(const float* __restrict__ v, const float* __restrict__ g) {
    int oc = threadIdx.x;   // 64 threads
    float s = 0.f;
    for (int kk = 0; kk < 192; kk++) { float vv = v[oc*192+kk]; s += vv*vv; }
    float sc = g[oc] / sqrtf(s);
    for (int k = 0; k < 3; k++) {
        for (int ii = 0; ii < 32; ii++) {
            float w0 = sc * v[oc*192 + (2*ii)*3 + k];
            float w1 = sc * v[oc*192 + (2*ii+1)*3 + k];
            uint32_t lo, hi = packsplit(w0, w1, lo);
            int byt = (k*8 + (oc >> 3))*1024 + SWZ128((oc & 7)*128 + ii*4);
            g_wimg[byt >> 2]        = hi;
            g_wimg[6144 + (byt >> 2)] = lo;
        }
    }
    if (oc == 0) {
        double su = g_red[0], ssq = g_red[1];
        double N = (double)NTOT;
        double m = su / N;
        double var = (ssq - su*su/N) / (N - 1.0);
        g_scal[0] = (float)(0.8 / m);
        g_scal[1] = (float)(0.8 / sqrt(var));
        g_scal[2] = (float)(0.2 * m / 0.8);
        g_scal[3] = (float)(0.2 * sqrt(var) / 0.8);
    }
}

// ------------ tensor-core conv via mma.sync, M-tile = 64 ------------
// D[m 0..63][oc 0..63] = sum_kk A[m][kk]*B[oc][kk], K = 192 (kk = k*64 + i)
// smem: Ahi@0 (24KB), Alo@24576, Bhi@49152 (24KB), Blo@73728. total 98304 (2 CTAs/SM).
#define SM_ALO 24576
#define SM_B   49152
#define SMEM_MMA 98304

template<int LEVEL>
__global__ void __launch_bounds__(256, 2) k_convmma(const float* __restrict__ x) {
    constexpr int L    = LEVEL ? 1024 : 2048;
    constexpr int OCL  = LEVEL ? 1533 : 3069;
    constexpr int OSTR = LEVEL ? 1536 : 3072;
    float* cout = LEVEL ? g_c1 : g_c0;

    extern __shared__ char sm[];
    const int tid = threadIdx.x, wid = tid >> 5, lane = tid & 31;
    const int b = blockIdx.y, o0 = blockIdx.x * 64;

    // B images (48KB) from gmem
    {
        const uint4* wi = (const uint4*)g_wimg;
        uint4* bs = (uint4*)(sm + SM_B);
        #pragma unroll
        for (int it = 0; it < 12; it++) bs[tid + it*256] = wi[tid + it*256];
    }

    // build A hi/lo images: 64 rows x 96 channel-pairs
    const float f0c = g_scal[2], f2c = g_scal[3];
    const float2* xb2 = (const float2*)(x + (size_t)b * (TT*64));
    for (int e = tid; e < 6144; e += 256) {
        int m = e / 96, rem = e - m*96;
        int k = rem >> 5, ii = rem & 31;
        int u2 = (o0 + m) * 2;
        int r  = u2 % 3;
        int s  = u2 / 3 + k;
        float2 va = make_float2(0.f, 0.f);
        if (s < L) {
            int tp = LEVEL ? (s << 2) : (s << 1);
            float2 p = xb2[tp*32 + ii];
            if (r == 1) va = p;
            else {
                int ta = LEVEL ? (4*s + 3) : (2*s + 1);
                float2 a = xb2[ta*32 + ii];
                float f = (r == 0) ? f0c : f2c;
                va.x = fmaf(f, p.x, a.x);
                va.y = fmaf(f, p.y, a.y);
            }
        }
        uint32_t lo, hi = packsplit(va.x, va.y, lo);
        int byt = (k*8 + (m >> 3))*1024 + SWZ128((m & 7)*128 + ii*4);
        *(uint32_t*)(sm + byt)          = hi;
        *(uint32_t*)(sm + SM_ALO + byt) = lo;
    }
    __syncthreads();

    // mainloop: warp wid -> wm = wid>>1 (16 rows), nh = wid&1 (32 oc)
    const uint32_t sbase = smem_u32(sm);
    const int wm = wid >> 1, nh = wid & 1;
    const int l16 = lane & 15, lhi = lane >> 4;

    int arow = wm*16 + l16;
    uint32_t pa = sbase + (uint32_t)((arow >> 3)*1024)
                + ((uint32_t)(((arow & 7)*128) | (lhi*16)) ^ (uint32_t)((arow & 7) << 4));
    uint32_t pb[2];
    #pragma unroll
    for (int t = 0; t < 2; t++) {
        int brow = nh*32 + t*16 + l16;
        pb[t] = sbase + SM_B + (uint32_t)((brow >> 3)*1024)
              + ((uint32_t)(((brow & 7)*128) | (lhi*16)) ^ (uint32_t)((brow & 7) << 4));
    }

    float d[4][4];
    #pragma unroll
    for (int j = 0; j < 4; j++)
        #pragma unroll
        for (int q = 0; q < 4; q++) d[j][q] = 0.f;

    #pragma unroll 1
    for (int s = 0; s < 12; s++) {
        uint32_t ao = (uint32_t)(s >> 2) * 8192;
        uint32_t bo = (uint32_t)(s >> 2) * 8192;
        uint32_t cb = (uint32_t)(s & 3) * 32;
        uint32_t AH[4], AL[4], BH0[4], BH1[4], BL0[4], BL1[4];
        uint32_t aa = (pa ^ cb) + ao;
        uint32_t b0 = (pb[0] ^ cb) + bo, b1 = (pb[1] ^ cb) + bo;
        LDSM4(AH, aa); LDSM4(AL, aa + SM_ALO);
        LDSM4(BH0, b0); LDSM4(BH1, b1);
        LDSM4(BL0, b0 + 24576); LDSM4(BL1, b1 + 24576);

        // pass1: Ah*Bh
        MMA16816(d[0], AH, BH0[0], BH0[2]);
        MMA16816(d[1], AH, BH0[1], BH0[3]);
        MMA16816(d[2], AH, BH1[0], BH1[2]);
        MMA16816(d[3], AH, BH1[1], BH1[3]);
        // pass2: Ah*Bl
        MMA16816(d[0], AH, BL0[0], BL0[2]);
        MMA16816(d[1], AH, BL0[1], BL0[3]);
        MMA16816(d[2], AH, BL1[0], BL1[2]);
        MMA16816(d[3], AH, BL1[1], BL1[3]);
        // pass3: Al*Bh
        MMA16816(d[0], AL, BH0[0], BH0[2]);
        MMA16816(d[1], AL, BH0[1], BH0[3]);
        MMA16816(d[2], AL, BH1[0], BH1[2]);
        MMA16816(d[3], AL, BH1[1], BH1[3]);
    }
    __syncthreads();

    // epilogue: scale by row class, transpose via smem, store
    const float cm = g_scal[0], cs = g_scal[1];
    float* tp = (float*)sm;                  // [64 oc][68], reuses A region
    {
        int m0 = wm*16 + (lane >> 2);
        int r0 = (2*(o0 + m0)) % 3;
        int r8 = (2*(o0 + m0 + 8)) % 3;
        float f0 = (r0 == 0) ? cm : ((r0 == 2) ? cs : 1.f);
        float f8 = (r8 == 0) ? cm : ((r8 == 2) ? cs : 1.f);
        #pragma unroll
        for (int nt = 0; nt < 4; nt++) {
            int oc0 = nh*32 + nt*8 + (lane & 3)*2;
            tp[oc0*68 + m0]         = f0 * d[nt][0];
            tp[(oc0+1)*68 + m0]     = f0 * d[nt][1];
            tp[oc0*68 + m0 + 8]     = f8 * d[nt][2];
            tp[(oc0+1)*68 + m0 + 8] = f8 * d[nt][3];
        }
    }
    __syncthreads();
    for (int e = tid; e < 4096; e += 256) {
        int oc = e >> 6, ml = e & 63;
        int o = o0 + ml;
        if (o < OCL) cout[((size_t)(b*64 + oc))*OSTR + o] = tp[oc*68 + ml];
    }
}

// ------------ pool + gauss + BN stats ------------
template<int LEVEL>
__global__ void __launch_bounds__(256) k_pool(const float* __restrict__ bias) {
    constexpr int P    = LEVEL ? 767  : 1535;
    constexpr int PSTR = LEVEL ? 768  : 1536;
    constexpr int OCL  = LEVEL ? 1533 : 3069;
    constexpr int OSTR = LEVEL ? 1536 : 3072;
    constexpr int DUP  = LEVEL ? 512  : 1024;
    const float* cin = LEVEL ? g_c1 : g_c0;
    float* z = LEVEL ? g_z1 : g_z0;

    int row = blockIdx.y;
    int oc  = row & 63;
    int tid = threadIdx.x;
    int p   = blockIdx.x * 256 + tid;
    float sv = 0.f, ssv = 0.f;
    if (p < P) {
        const float* cr = cin + (size_t)row * OSTR;
        float m = cr[2*p];
        if (p > 0)         m = fmaxf(m, cr[2*p - 1]);
        if (2*p + 1 < OCL) m = fmaxf(m, cr[2*p + 1]);
        m += bias[oc];
        float e  = m > 0.f ? m : expm1f(m);
        float zz = expf(-0.5f * e * e);
        z[(size_t)row * PSTR + p] = zz;
        float w = (p <= DUP && !(p & 1)) ? 2.f : 1.f;
        sv = w * zz; ssv = w * zz * zz;
    }
    __shared__ float r1[256], r2[256];
    r1[tid] = sv; r2[tid] = ssv; __syncthreads();
    for (int o = 128; o > 0; o >>= 1) {
        if (tid < o) { r1[tid] += r1[tid+o]; r2[tid] += r2[tid+o]; }
        __syncthreads();
    }
    if (tid == 0) {
        atomicAdd(&g_bns[LEVEL*128 + oc],      (double)r1[0]);
        atomicAdd(&g_bns[LEVEL*128 + 64 + oc], (double)r2[0]);
    }
}

__global__ void k_bnfin(const float* __restrict__ gamma, const float* __restrict__ beta) {
    int oc = threadIdx.x;
    #pragma unroll
    for (int l = 0; l < 2; l++) {
        double cnt = l ? 65536.0 : 131072.0;
        double su = g_bns[l*128 + oc], ssq = g_bns[l*128 + 64 + oc];
        double mu = su / cnt;
        double var = ssq / cnt - mu*mu;
        double inv = 1.0 / sqrt(var + 1e-5);
        g_bnp[l*128 + oc]      = (float)((double)gamma[oc] * inv);
        g_bnp[l*128 + 64 + oc] = (float)((double)beta[oc] - mu * (double)gamma[oc] * inv);
    }
}

// ------------ final assembly ------------
__global__ void __launch_bounds__(256) k_asm(const float* __restrict__ x,
                                             float* __restrict__ out) {
    __shared__ float tile[64][65];
    __shared__ int sT[64];
    __shared__ int sPL[64];
    int b  = blockIdx.y;
    int f0 = blockIdx.x * 64;
    int tid = threadIdx.x;

    if (tid < 64) {
        int f = f0 + tid;
        int part, j;
        if (f == 0)      { part = 0; j = 0; }
        else if (f == 1) { part = 1; j = 0; }
        else if (f < 5462) {
            int k = (f - 2) / 12;
            int r = (f - 2) - 12*k;
            if      (r < 4)   { part = 0; j = 9*k + 1 + r; }
            else if (r == 4)  { part = 1; j = 3*k + 1; }
            else if (r < 9)   { part = 0; j = 9*k + r; }
            else if (r == 9)  { part = 1; j = 3*k + 2; }
            else if (r == 10) { part = 0; j = 9*k + 9; }
            else              { part = 1; j = 3*k + 3; }
        } else { part = 1; j = 1366 + (f - 5462); }
        int t, pl = -1;
        if (part == 0) {
            t = j;
            if (j & 1) {
                int q = j >> 1;
                int p = (q < 1539) ? 2*(q/3) + ((q % 3) == 2) : q - 513;
                pl = p*2;
            }
        } else {
            t = 2*j + (j & 1);
            if (j & 1) {
                int q = j >> 1;
                int p = (q < 771) ? 2*(q/3) + ((q % 3) == 2) : q - 257;
                pl = p*2 + 1;
            }
        }
        sT[tid] = t; sPL[tid] = pl;
    }
    __syncthreads();

    const float* xb = x + (size_t)b * (TT*64);
    int c = tid & 63, fg = tid >> 6;
    #pragma unroll
    for (int it = 0; it < 16; it++) {
        int fl = fg * 16 + it;
        tile[fl][c] = xb[sT[fl]*64 + c];
    }
    __syncthreads();

    for (int it = 0; it < 16; it++) {
        int e  = it * 256 + tid;
        int cc = e >> 6, fl = e & 63;
        float v = tile[fl][cc];
        int pl = sPL[fl];
        if (pl >= 0) {
            int lvl = pl & 1, p = pl >> 1;
            const float* z = lvl ? g_z1 : g_z0;
            int stride = lvl ? 768 : 1536;
            float zz = z[(size_t)(b*64 + cc)*stride + p];
            float sc = g_bnp[lvl*128 + cc], sh = g_bnp[lvl*128 + 64 + cc];
            float bn = fmaf(sc, zz, sh);
            v += bn > 0.f ? bn : expm1f(bn);
        }
        out[((size_t)(b*64 + cc))*6144 + f0 + fl] = v;
    }
}

extern "C" void kernel_launch(void* const* d_in, const int* in_sizes, int n_in,
                              void* d_out, int out_size) {
    const float* x        = (const float*)d_in[0];
    const float* conv_v   = (const float*)d_in[1];
    const float* conv_g   = (const float*)d_in[2];
    const float* conv_b   = (const float*)d_in[3];
    const float* bn_gamma = (const float*)d_in[4];
    const float* bn_beta  = (const float*)d_in[5];
    float* out = (float*)d_out;

    cudaFuncSetAttribute(k_convmma<0>, cudaFuncAttributeMaxDynamicSharedMemorySize, SMEM_MMA);
    cudaFuncSetAttribute(k_convmma<1>, cudaFuncAttributeMaxDynamicSharedMemorySize, SMEM_MMA);

    k_init<<<1, 256>>>();
    k_reduce<<<1024, 256>>>(x);
    k_wnorm<<<1, 64>>>(conv_v, conv_g);
    k_convmma<0><<<dim3(48, 64), 256, SMEM_MMA>>>(x);
    k_convmma<1><<<dim3(24, 64), 256, SMEM_MMA>>>(x);
    k_pool<0><<<dim3(6, 4096), 256>>>(conv_b);
    k_pool<1><<<dim3(3, 4096), 256>>>(conv_b);
    k_bnfin<<<1, 64>>>(bn_gamma, bn_beta);
    k_asm<<<dim3(96, 64), 256>>>(x, out);
}

// round 7
// speedup vs baseline: 1.7562x; 1.0923x over previous
#include <cuda_runtime.h>
#include <cuda_fp16.h>
#include <cstdint>
#include <math.h>

#define BB 64
#define TT 4096
#define NTOT (BB*TT*64)

// ------------ device scratch ------------
__device__ double   g_red[2];
__device__ float    g_scal[4];            // cm, cs, 0.2/cm, 0.2/cs
__device__ uint32_t g_wimg[2*6144];       // B images (hi, lo), 24KB each, pre-swizzled fp16x2
__device__ float    g_c0[64*64*3072];     // conv0 out [b*64+oc][o], 3069 valid, stride 3072
__device__ float    g_c1[64*64*1536];     // conv1 out, 1533 valid, stride 1536
__device__ float    g_z0[64*1536*64];     // gauss lvl0 [b][p][oc], 1535 valid p
__device__ float    g_z1[64*768*64];      // gauss lvl1 [b][p][oc], 767 valid p
__device__ double   g_bns[256];
__device__ float    g_bnp[256];

#define SWZ128(o) ((o) ^ (((o) >> 3) & 0x70))

__device__ __forceinline__ uint32_t smem_u32(const void* p) {
    uint32_t a;
    asm("{ .reg .u64 t; cvta.to.shared.u64 t, %1; cvt.u32.u64 %0, t; }" : "=r"(a) : "l"(p));
    return a;
}

#define LDSM4(r, a) asm volatile( \
    "ldmatrix.sync.aligned.m8n8.x4.shared.b16 {%0,%1,%2,%3}, [%4];" \
    : "=r"((r)[0]), "=r"((r)[1]), "=r"((r)[2]), "=r"((r)[3]) : "r"(a))

#define MMA16816(d, a, b0, b1) asm volatile( \
    "mma.sync.aligned.m16n8k16.row.col.f32.f16.f16.f32 " \
    "{%0,%1,%2,%3}, {%4,%5,%6,%7}, {%8,%9}, {%0,%1,%2,%3};" \
    : "+f"((d)[0]), "+f"((d)[1]), "+f"((d)[2]), "+f"((d)[3]) \
    : "r"((a)[0]), "r"((a)[1]), "r"((a)[2]), "r"((a)[3]), "r"(b0), "r"(b1))

__device__ __forceinline__ uint32_t packsplit(float vx, float vy, uint32_t& lo) {
    __half h0 = __float2half_rn(vx); float r0 = vx - __half2float(h0);
    __half h1 = __float2half_rn(vy); float r1 = vy - __half2float(h1);
    __half g0 = __float2half_rn(r0);
    __half g1 = __float2half_rn(r1);
    lo = (uint32_t)__half_as_ushort(g0) | ((uint32_t)__half_as_ushort(g1) << 16);
    return (uint32_t)__half_as_ushort(h0) | ((uint32_t)__half_as_ushort(h1) << 16);
}

// ------------ small kernels ------------
__global__ void k_init() {
    int t = threadIdx.x;
    if (t < 2) g_red[t] = 0.0;
    g_bns[t] = 0.0;
}

__global__ void __launch_bounds__(256) k_reduce(const float* __restrict__ x) {
    float s = 0.f, ss = 0.f;
    const float4* x4 = (const float4*)x;
    const int n4 = NTOT / 4;
    for (int i = blockIdx.x * 256 + threadIdx.x; i < n4; i += gridDim.x * 256) {
        float4 v = x4[i];
        s  += (v.x + v.y) + (v.z + v.w);
        ss += (v.x*v.x + v.y*v.y) + (v.z*v.z + v.w*v.w);
    }
    __shared__ float r1[256], r2[256];
    int tid = threadIdx.x;
    r1[tid] = s; r2[tid] = ss; __syncthreads();
    for (int o = 128; o > 0; o >>= 1) {
        if (tid < o) { r1[tid] += r1[tid+o]; r2[tid] += r2[tid+o]; }
        __syncthreads();
    }
    if (tid == 0) {
        atomicAdd(&g_red[0], (double)r1[0]);
        atomicAdd(&g_red[1], (double)r2[0]);
    }
}

// weight-norm + build swizzled fp16 hi/lo B images: B[oc][kk = k*64 + i]
__global__ void k_wnorm(const float* __restrict__ v, const float* __restrict__ g) {
    int oc = threadIdx.x;   // 64 threads
    float s = 0.f;
    for (int kk = 0; kk < 192; kk++) { float vv = v[oc*192+kk]; s += vv*vv; }
    float sc = g[oc] / sqrtf(s);
    for (int k = 0; k < 3; k++) {
        for (int ii = 0; ii < 32; ii++) {
            float w0 = sc * v[oc*192 + (2*ii)*3 + k];
            float w1 = sc * v[oc*192 + (2*ii+1)*3 + k];
            uint32_t lo, hi = packsplit(w0, w1, lo);
            int byt = (k*8 + (oc >> 3))*1024 + SWZ128((oc & 7)*128 + ii*4);
            g_wimg[byt >> 2]        = hi;
            g_wimg[6144 + (byt >> 2)] = lo;
        }
    }
    if (oc == 0) {
        double su = g_red[0], ssq = g_red[1];
        double N = (double)NTOT;
        double m = su / N;
        double var = (ssq - su*su/N) / (N - 1.0);
        g_scal[0] = (float)(0.8 / m);
        g_scal[1] = (float)(0.8 / sqrt(var));
        g_scal[2] = (float)(0.2 * m / 0.8);
        g_scal[3] = (float)(0.2 * sqrt(var) / 0.8);
    }
}

// ------------ tensor-core conv via mma.sync, M-tile = 64, double-buffered ------------
#define SM_ALO 24576
#define SM_B   49152
#define SMEM_MMA 98304

template<int LEVEL>
__global__ void __launch_bounds__(256, 2) k_convmma(const float* __restrict__ x) {
    constexpr int L    = LEVEL ? 1024 : 2048;
    constexpr int OCL  = LEVEL ? 1533 : 3069;
    constexpr int OSTR = LEVEL ? 1536 : 3072;
    float* cout = LEVEL ? g_c1 : g_c0;

    extern __shared__ char sm[];
    const int tid = threadIdx.x, wid = tid >> 5, lane = tid & 31;
    const int b = blockIdx.y, o0 = blockIdx.x * 64;

    // B images (48KB) from gmem
    {
        const uint4* wi = (const uint4*)g_wimg;
        uint4* bs = (uint4*)(sm + SM_B);
        #pragma unroll
        for (int it = 0; it < 12; it++) bs[tid + it*256] = wi[tid + it*256];
    }

    // build A hi/lo images: 64 rows x 96 channel-pairs
    const float f0c = g_scal[2], f2c = g_scal[3];
    const float2* xb2 = (const float2*)(x + (size_t)b * (TT*64));
    for (int e = tid; e < 6144; e += 256) {
        int m = e / 96, rem = e - m*96;
        int k = rem >> 5, ii = rem & 31;
        int u2 = (o0 + m) * 2;
        int r  = u2 % 3;
        int s  = u2 / 3 + k;
        float2 va = make_float2(0.f, 0.f);
        if (s < L) {
            int tp = LEVEL ? (s << 2) : (s << 1);
            float2 p = xb2[tp*32 + ii];
            if (r == 1) va = p;
            else {
                int ta = LEVEL ? (4*s + 3) : (2*s + 1);
                float2 a = xb2[ta*32 + ii];
                float f = (r == 0) ? f0c : f2c;
                va.x = fmaf(f, p.x, a.x);
                va.y = fmaf(f, p.y, a.y);
            }
        }
        uint32_t lo, hi = packsplit(va.x, va.y, lo);
        int byt = (k*8 + (m >> 3))*1024 + SWZ128((m & 7)*128 + ii*4);
        *(uint32_t*)(sm + byt)          = hi;
        *(uint32_t*)(sm + SM_ALO + byt) = lo;
    }
    __syncthreads();

    // mainloop: warp wid -> wm = wid>>1 (16 rows), nh = wid&1 (32 oc)
    const uint32_t sbase = smem_u32(sm);
    const int wm = wid >> 1, nh = wid & 1;
    const int l16 = lane & 15, lhi = lane >> 4;

    int arow = wm*16 + l16;
    const uint32_t pa = sbase + (uint32_t)((arow >> 3)*1024)
                + ((uint32_t)(((arow & 7)*128) | (lhi*16)) ^ (uint32_t)((arow & 7) << 4));
    uint32_t pbt[2];
    #pragma unroll
    for (int t = 0; t < 2; t++) {
        int brow = nh*32 + t*16 + l16;
        pbt[t] = sbase + SM_B + (uint32_t)((brow >> 3)*1024)
              + ((uint32_t)(((brow & 7)*128) | (lhi*16)) ^ (uint32_t)((brow & 7) << 4));
    }
    const uint32_t pb0 = pbt[0], pb1 = pbt[1];

    float d[4][4];
    #pragma unroll
    for (int j = 0; j < 4; j++)
        #pragma unroll
        for (int q = 0; q < 4; q++) d[j][q] = 0.f;

    uint32_t AH[2][4], AL[2][4], BH0[2][4], BH1[2][4], BL0[2][4], BL1[2][4];

#define LOADSTEP(buf, s) do { \
        uint32_t ao = (uint32_t)((s) >> 2) * 8192; \
        uint32_t cb = (uint32_t)((s) & 3) * 32; \
        uint32_t aa = (pa ^ cb) + ao; \
        uint32_t bb0 = (pb0 ^ cb) + ao, bb1 = (pb1 ^ cb) + ao; \
        LDSM4(AH[buf], aa); LDSM4(AL[buf], aa + SM_ALO); \
        LDSM4(BH0[buf], bb0); LDSM4(BH1[buf], bb1); \
        LDSM4(BL0[buf], bb0 + 24576); LDSM4(BL1[buf], bb1 + 24576); \
    } while (0)

#define MMASTEP(c) do { \
        MMA16816(d[0], AH[c], BH0[c][0], BH0[c][2]); \
        MMA16816(d[1], AH[c], BH0[c][1], BH0[c][3]); \
        MMA16816(d[2], AH[c], BH1[c][0], BH1[c][2]); \
        MMA16816(d[3], AH[c], BH1[c][1], BH1[c][3]); \
        MMA16816(d[0], AH[c], BL0[c][0], BL0[c][2]); \
        MMA16816(d[1], AH[c], BL0[c][1], BL0[c][3]); \
        MMA16816(d[2], AH[c], BL1[c][0], BL1[c][2]); \
        MMA16816(d[3], AH[c], BL1[c][1], BL1[c][3]); \
        MMA16816(d[0], AL[c], BH0[c][0], BH0[c][2]); \
        MMA16816(d[1], AL[c], BH0[c][1], BH0[c][3]); \
        MMA16816(d[2], AL[c], BH1[c][0], BH1[c][2]); \
        MMA16816(d[3], AL[c], BH1[c][1], BH1[c][3]); \
    } while (0)

    LOADSTEP(0, 0);
    #pragma unroll
    for (int s = 0; s < 12; s++) {
        const int cur = s & 1, nx = cur ^ 1;
        if (s < 11) LOADSTEP(nx, s + 1);
        MMASTEP(cur);
    }
#undef LOADSTEP
#undef MMASTEP
    __syncthreads();

    // epilogue: scale by row class, transpose via smem, store
    const float cm = g_scal[0], cs = g_scal[1];
    float* tp = (float*)sm;                  // [64 oc][68], reuses A region
    {
        int m0 = wm*16 + (lane >> 2);
        int r0 = (2*(o0 + m0)) % 3;
        int r8 = (2*(o0 + m0 + 8)) % 3;
        float f0 = (r0 == 0) ? cm : ((r0 == 2) ? cs : 1.f);
        float f8 = (r8 == 0) ? cm : ((r8 == 2) ? cs : 1.f);
        #pragma unroll
        for (int nt = 0; nt < 4; nt++) {
            int oc0 = nh*32 + nt*8 + (lane & 3)*2;
            tp[oc0*68 + m0]         = f0 * d[nt][0];
            tp[(oc0+1)*68 + m0]     = f0 * d[nt][1];
            tp[oc0*68 + m0 + 8]     = f8 * d[nt][2];
            tp[(oc0+1)*68 + m0 + 8] = f8 * d[nt][3];
        }
    }
    __syncthreads();
    for (int e = tid; e < 4096; e += 256) {
        int oc = e >> 6, ml = e & 63;
        int o = o0 + ml;
        if (o < OCL) cout[((size_t)(b*64 + oc))*OSTR + o] = tp[oc*68 + ml];
    }
}

// ------------ pool + gauss + BN stats; z written as [b][p][oc] ------------
template<int LEVEL>
__global__ void __launch_bounds__(256) k_pool(const float* __restrict__ bias) {
    constexpr int P    = LEVEL ? 767  : 1535;
    constexpr int PSTR = LEVEL ? 768  : 1536;
    constexpr int OCL  = LEVEL ? 1533 : 3069;
    constexpr int OSTR = LEVEL ? 1536 : 3072;
    constexpr int DUP  = LEVEL ? 512  : 1024;
    const float* cin = LEVEL ? g_c1 : g_c0;
    float* z = LEVEL ? g_z1 : g_z0;

    __shared__ float raw[64*133];
    __shared__ float rs[512];
    int b  = blockIdx.y;
    int p0 = blockIdx.x * 64;
    int tid = threadIdx.x;

    // load conv rows [oc][o = 2p0-1 .. 2p0+127], coalesced per row
    const float* cbase = cin + ((size_t)b*64)*OSTR;
    for (int e = tid; e < 64*130; e += 256) {
        int row = e / 130, j = e - row*130;
        int o = 2*p0 - 1 + j;
        float v = -1e30f;
        if (o >= 0 && o < OCL) v = cbase[(size_t)row*OSTR + o];
        raw[row*133 + j] = v;
    }
    __syncthreads();

    int oc = tid & 63, pg = tid >> 6;
    float bi = bias[oc];
    float sv = 0.f, ssv = 0.f;
    #pragma unroll
    for (int i = 0; i < 16; i++) {
        int pl = pg*16 + i;
        int p  = p0 + pl;
        if (p < P) {
            float m = fmaxf(fmaxf(raw[oc*133 + 2*pl], raw[oc*133 + 2*pl + 1]),
                            raw[oc*133 + 2*pl + 2]);
            m += bi;
            float e  = m > 0.f ? m : expm1f(m);
            float zz = expf(-0.5f * e * e);
            z[((size_t)b*PSTR + p)*64 + oc] = zz;
            float w = (p <= DUP && !(p & 1)) ? 2.f : 1.f;
            sv += w * zz; ssv += w * zz * zz;
        }
    }
    rs[tid] = sv; rs[256 + tid] = ssv;
    __syncthreads();
    if (tid < 64) {
        float s1 = rs[tid] + rs[tid+64] + rs[tid+128] + rs[tid+192];
        float s2 = rs[256+tid] + rs[320+tid] + rs[384+tid] + rs[448+tid];
        atomicAdd(&g_bns[LEVEL*128 + tid],      (double)s1);
        atomicAdd(&g_bns[LEVEL*128 + 64 + tid], (double)s2);
    }
}

__global__ void k_bnfin(const float* __restrict__ gamma, const float* __restrict__ beta) {
    int oc = threadIdx.x;
    #pragma unroll
    for (int l = 0; l < 2; l++) {
        double cnt = l ? 65536.0 : 131072.0;
        double su = g_bns[l*128 + oc], ssq = g_bns[l*128 + 64 + oc];
        double mu = su / cnt;
        double var = ssq / cnt - mu*mu;
        double inv = 1.0 / sqrt(var + 1e-5);
        g_bnp[l*128 + oc]      = (float)((double)gamma[oc] * inv);
        g_bnp[l*128 + 64 + oc] = (float)((double)beta[oc] - mu * (double)gamma[oc] * inv);
    }
}

// ------------ final assembly ------------
__global__ void __launch_bounds__(256) k_asm(const float* __restrict__ x,
                                             float* __restrict__ out) {
    __shared__ float tile[64][65];
    __shared__ int sT[64];
    __shared__ int sPL[64];
    int b  = blockIdx.y;
    int f0 = blockIdx.x * 64;
    int tid = threadIdx.x;

    if (tid < 64) {
        int f = f0 + tid;
        int part, j;
        if (f == 0)      { part = 0; j = 0; }
        else if (f == 1) { part = 1; j = 0; }
        else if (f < 5462) {
            int k = (f - 2) / 12;
            int r = (f - 2) - 12*k;
            if      (r < 4)   { part = 0; j = 9*k + 1 + r; }
            else if (r == 4)  { part = 1; j = 3*k + 1; }
            else if (r < 9)   { part = 0; j = 9*k + r; }
            else if (r == 9)  { part = 1; j = 3*k + 2; }
            else if (r == 10) { part = 0; j = 9*k + 9; }
            else              { part = 1; j = 3*k + 3; }
        } else { part = 1; j = 1366 + (f - 5462); }
        int t, pl = -1;
        if (part == 0) {
            t = j;
            if (j & 1) {
                int q = j >> 1;
                int p = (q < 1539) ? 2*(q/3) + ((q % 3) == 2) : q - 513;
                pl = p*2;
            }
        } else {
            t = 2*j + (j & 1);
            if (j & 1) {
                int q = j >> 1;
                int p = (q < 771) ? 2*(q/3) + ((q % 3) == 2) : q - 257;
                pl = p*2 + 1;
            }
        }
        sT[tid] = t; sPL[tid] = pl;
    }
    __syncthreads();

    const float* xb = x + (size_t)b * (TT*64);
    int c = tid & 63, fg = tid >> 6;
    #pragma unroll
    for (int it = 0; it < 16; it++) {
        int fl = fg * 16 + it;
        tile[fl][c] = xb[sT[fl]*64 + c];
    }
    __syncthreads();

    for (int it = 0; it < 16; it++) {
        int e  = it * 256 + tid;
        int cc = e >> 6, fl = e & 63;
        float v = tile[fl][cc];
        int pl = sPL[fl];
        if (pl >= 0) {
            int lvl = pl & 1, p = pl >> 1;
            const float* z = lvl ? g_z1 : g_z0;
            int stride = lvl ? 768 : 1536;
            float zz = z[((size_t)b*stride + p)*64 + cc];
            float sc = g_bnp[lvl*128 + cc], sh = g_bnp[lvl*128 + 64 + cc];
            float bn = fmaf(sc, zz, sh);
            v += bn > 0.f ? bn : expm1f(bn);
        }
        out[((size_t)(b*64 + cc))*6144 + f0 + fl] = v;
    }
}

extern "C" void kernel_launch(void* const* d_in, const int* in_sizes, int n_in,
                              void* d_out, int out_size) {
    const float* x        = (const float*)d_in[0];
    const float* conv_v   = (const float*)d_in[1];
    const float* conv_g   = (const float*)d_in[2];
    const float* conv_b   = (const float*)d_in[3];
    const float* bn_gamma = (const float*)d_in[4];
    const float* bn_beta  = (const float*)d_in[5];
    float* out = (float*)d_out;

    cudaFuncSetAttribute(k_convmma<0>, cudaFuncAttributeMaxDynamicSharedMemorySize, SMEM_MMA);
    cudaFuncSetAttribute(k_convmma<1>, cudaFuncAttributeMaxDynamicSharedMemorySize, SMEM_MMA);

    k_init<<<1, 256>>>();
    k_reduce<<<1024, 256>>>(x);
    k_wnorm<<<1, 64>>>(conv_v, conv_g);
    k_convmma<0><<<dim3(48, 64), 256, SMEM_MMA>>>(x);
    k_convmma<1><<<dim3(24, 64), 256, SMEM_MMA>>>(x);
    k_pool<0><<<dim3(24, 64), 256>>>(conv_b);
    k_pool<1><<<dim3(12, 64), 256>>>(conv_b);
    k_bnfin<<<1, 64>>>(bn_gamma, bn_beta);
    k_asm<<<dim3(96, 64), 256>>>(x, out);
}